// round 2
// baseline (speedup 1.0000x reference)
#include <cuda_runtime.h>
#include <cuda_fp16.h>
#include <math.h>

#define LMAX      524288
#define NB_STEP   592
#define NT_STEP   256
#define NB_PROJ   1184
#define NT_PROJ   256
#define RELMAX    64

// fp16 storage for projected K(+bias) and V: [L][32] halves, row-major.
__device__ __half g_kb[(size_t)LMAX * 32];
__device__ __half g_v [(size_t)LMAX * 32];
// per-block partials: block b, head h: {s, acc[8]} padded to 12 floats
__device__ float  g_part[NB_STEP * 4 * 12];
__device__ float  g_z[32];
__device__ float  g_q[32];   // prescaled by 0.5 (= 1/sqrt(HEAD))

// -------------------- init: z = candidate; q0 = 0.5*(cand @ q_w.T + q_b) ----
__global__ void k_init(const float* __restrict__ cand,
                       const float* __restrict__ q_w,
                       const float* __restrict__ q_b)
{
    int j = threadIdx.x;
    if (j >= 32) return;
    g_z[j] = cand[j];
    float acc = q_b[j];
#pragma unroll
    for (int i = 0; i < 32; i++) acc += cand[i] * q_w[j * 32 + i];
    g_q[j] = 0.5f * acc;
}

// -------------------- prologue: kb = zp@k_w.T + k_b + rel_bias[idx]; v = zp@v_w.T + v_b
__global__ __launch_bounds__(NT_PROJ)
void k_project(const float* __restrict__ zp,
               const float* __restrict__ k_w, const float* __restrict__ k_b,
               const float* __restrict__ v_w, const float* __restrict__ v_b,
               const float* __restrict__ rel_bias,
               const int*   __restrict__ pos, int L)
{
    __shared__ float swk[1024];
    __shared__ float swv[1024];
    __shared__ float sbk[32];
    __shared__ float sbv[32];
    for (int t = threadIdx.x; t < 1024; t += NT_PROJ) { swk[t] = k_w[t]; swv[t] = v_w[t]; }
    if (threadIdx.x < 32)      sbk[threadIdx.x]      = k_b[threadIdx.x];
    else if (threadIdx.x < 64) sbv[threadIdx.x - 32] = v_b[threadIdx.x - 32];
    __syncthreads();

    const int off    = pos[0] - L + RELMAX;
    const int stride = gridDim.x * blockDim.x;

    for (int l = blockIdx.x * blockDim.x + threadIdx.x; l < L; l += stride) {
        float x[32];
        const float4* row = (const float4*)(zp + (size_t)l * 32);
#pragma unroll
        for (int c = 0; c < 8; c++) {
            float4 t = row[c];
            x[4*c+0] = t.x; x[4*c+1] = t.y; x[4*c+2] = t.z; x[4*c+3] = t.w;
        }
        int idx = off + l;
        idx = idx < 0 ? 0 : (idx > 2 * RELMAX ? 2 * RELMAX : idx);
        const float* rb = rel_bias + idx * 32;

        float ko[32], vo[32];
#pragma unroll
        for (int j = 0; j < 32; j++) {
            const float4* wr = (const float4*)(swk + j * 32);
            float p0 = 0.f, p1 = 0.f, p2 = 0.f, p3 = 0.f;
#pragma unroll
            for (int c = 0; c < 8; c++) {
                float4 w = wr[c];
                p0 += x[4*c+0] * w.x;
                p1 += x[4*c+1] * w.y;
                p2 += x[4*c+2] * w.z;
                p3 += x[4*c+3] * w.w;
            }
            ko[j] = sbk[j] + rb[j] + ((p0 + p1) + (p2 + p3));
        }
#pragma unroll
        for (int j = 0; j < 32; j++) {
            const float4* wr = (const float4*)(swv + j * 32);
            float p0 = 0.f, p1 = 0.f, p2 = 0.f, p3 = 0.f;
#pragma unroll
            for (int c = 0; c < 8; c++) {
                float4 w = wr[c];
                p0 += x[4*c+0] * w.x;
                p1 += x[4*c+1] * w.y;
                p2 += x[4*c+2] * w.z;
                p3 += x[4*c+3] * w.w;
            }
            vo[j] = sbv[j] + ((p0 + p1) + (p2 + p3));
        }
        // pack to fp16 and store (32 halves = 4 int4 each)
        __half2 hk[16], hv[16];
#pragma unroll
        for (int m = 0; m < 16; m++) {
            hk[m] = __float22half2_rn(make_float2(ko[2*m], ko[2*m+1]));
            hv[m] = __float22half2_rn(make_float2(vo[2*m], vo[2*m+1]));
        }
        int4* dk = (int4*)(g_kb + (size_t)l * 32);
        int4* dv = (int4*)(g_v  + (size_t)l * 32);
        const int4* sk = (const int4*)hk;
        const int4* sv = (const int4*)hv;
#pragma unroll
        for (int c = 0; c < 4; c++) { dk[c] = sk[c]; dv[c] = sv[c]; }
    }
}

// -------------------- streaming attention step: partial {s, acc} per block --
__global__ __launch_bounds__(NT_STEP)
void k_step(int L)
{
    float q[32];
#pragma unroll
    for (int i = 0; i < 32; i++) q[i] = g_q[i];

    float s[4]      = {0.f, 0.f, 0.f, 0.f};
    float acc[4][8];
#pragma unroll
    for (int h = 0; h < 4; h++)
#pragma unroll
        for (int k = 0; k < 8; k++) acc[h][k] = 0.f;

    const int stride = gridDim.x * blockDim.x;
    for (int l = blockIdx.x * blockDim.x + threadIdx.x; l < L; l += stride) {
        int4 kr[4], vr[4];
        const int4* kp = (const int4*)(g_kb + (size_t)l * 32);
        const int4* vp = (const int4*)(g_v  + (size_t)l * 32);
#pragma unroll
        for (int c = 0; c < 4; c++) { kr[c] = kp[c]; vr[c] = vp[c]; }
        const __half2* kh = (const __half2*)kr;
        const __half2* vh = (const __half2*)vr;
#pragma unroll
        for (int h = 0; h < 4; h++) {
            float sc = 0.f;
#pragma unroll
            for (int m = 0; m < 4; m++) {
                float2 kf = __half22float2(kh[4*h + m]);
                sc += kf.x * q[8*h + 2*m] + kf.y * q[8*h + 2*m + 1];
            }
            float e = __expf(sc);   // bounded scores: no max-subtraction needed
            s[h] += e;
#pragma unroll
            for (int m = 0; m < 4; m++) {
                float2 vf = __half22float2(vh[4*h + m]);
                acc[h][2*m]   += e * vf.x;
                acc[h][2*m+1] += e * vf.y;
            }
        }
    }

    // warp-level tree reduction of all 36 values
    float vals[36];
#pragma unroll
    for (int h = 0; h < 4; h++) {
        vals[h*9] = s[h];
#pragma unroll
        for (int k = 0; k < 8; k++) vals[h*9 + 1 + k] = acc[h][k];
    }
#pragma unroll
    for (int t = 0; t < 36; t++) {
#pragma unroll
        for (int o = 16; o; o >>= 1)
            vals[t] += __shfl_down_sync(0xffffffffu, vals[t], o);
    }

    __shared__ float sred[NT_STEP / 32][36];
    int wid = threadIdx.x >> 5;
    int lid = threadIdx.x & 31;
    if (lid == 0) {
#pragma unroll
        for (int t = 0; t < 36; t++) sred[wid][t] = vals[t];
    }
    __syncthreads();
    int t = threadIdx.x;
    if (t < 36) {
        float r = 0.f;
#pragma unroll
        for (int w = 0; w < NT_STEP / 32; w++) r += sred[w][t];
        g_part[blockIdx.x * 48 + (t / 9) * 12 + (t % 9)] = r;
    }
}

// -------------------- update: reduce partials, o-proj, mish, LN, next q -----
__global__ __launch_bounds__(256)
void k_update(const float* __restrict__ o_w, const float* __restrict__ o_b,
              const float* __restrict__ q_w, const float* __restrict__ q_b,
              const float* __restrict__ coupling,
              const float* __restrict__ norm_scale,
              float* __restrict__ outp, int last)
{
    __shared__ float psum[7][36];
    __shared__ float red[36];
    __shared__ float sout[32];
    __shared__ float sz[32];

    int tid = threadIdx.x;
    const int CHUNK = (NB_STEP + 6) / 7;   // 85
    if (tid < 252) {
        int c = tid % 36, ch = tid / 36;
        int h = c / 9, k = c % 9;
        int b0 = ch * CHUNK;
        int b1 = b0 + CHUNK; if (b1 > NB_STEP) b1 = NB_STEP;
        float r = 0.f;
        for (int b = b0; b < b1; b++) r += g_part[b * 48 + h * 12 + k];
        psum[ch][c] = r;
    }
    __syncthreads();
    if (tid < 36) {
        float r = 0.f;
#pragma unroll
        for (int ch = 0; ch < 7; ch++) r += psum[ch][tid];
        red[tid] = r;
    }
    __syncthreads();
    if (tid < 32) {
        int h = tid / 8;
        sout[tid] = red[h * 9 + 1 + (tid % 8)] / red[h * 9];
    }
    __syncthreads();
    if (tid < 32) {
        float m = o_b[tid];
#pragma unroll
        for (int i = 0; i < 32; i++) m += sout[i] * o_w[tid * 32 + i];
        float zz = g_z[tid] + coupling[0] * m;
        float sp = (zz > 15.f) ? zz : log1pf(__expf(zz));
        zz = zz * tanhf(sp);
        sz[tid] = zz;
    }
    __syncthreads();
    if (tid < 32) {
        int par = tid & 1;
        float mn = 0.f;
#pragma unroll
        for (int d = 0; d < 16; d++) mn += sz[2 * d + par];
        mn *= (1.f / 16.f);
        float var = 0.f;
#pragma unroll
        for (int d = 0; d < 16; d++) { float dd = sz[2 * d + par] - mn; var += dd * dd; }
        var *= (1.f / 16.f);
        float zn = (sz[tid] - mn) * rsqrtf(var + 1e-5f) * norm_scale[0];
        g_z[tid] = zn;
        sout[tid] = zn;          // reuse as LN'd z for next-q
        if (last) outp[tid] = zn;
    }
    __syncthreads();
    if (tid < 32) {
        float qq = q_b[tid];
#pragma unroll
        for (int i = 0; i < 32; i++) qq += sout[i] * q_w[tid * 32 + i];
        g_q[tid] = 0.5f * qq;
    }
}

extern "C" void kernel_launch(void* const* d_in, const int* in_sizes, int n_in,
                              void* d_out, int out_size)
{
    const float* cand   = (const float*)d_in[0];
    const float* zp     = (const float*)d_in[1];
    const float* q_w    = (const float*)d_in[2];
    const float* q_b    = (const float*)d_in[3];
    const float* k_w    = (const float*)d_in[4];
    const float* k_b    = (const float*)d_in[5];
    const float* v_w    = (const float*)d_in[6];
    const float* v_b    = (const float*)d_in[7];
    const float* o_w    = (const float*)d_in[8];
    const float* o_b    = (const float*)d_in[9];
    const float* rbias  = (const float*)d_in[10];
    const float* coup   = (const float*)d_in[11];
    const float* nscale = (const float*)d_in[12];
    const int*   pos    = (const int*)  d_in[13];

    int L = in_sizes[1] / 32;
    float* outp = (float*)d_out;

    k_init<<<1, 32>>>(cand, q_w, q_b);
    k_project<<<NB_PROJ, NT_PROJ>>>(zp, k_w, k_b, v_w, v_b, rbias, pos, L);
    for (int s = 0; s < 8; s++) {
        k_step<<<NB_STEP, NT_STEP>>>(L);
        k_update<<<1, 256>>>(o_w, o_b, q_w, q_b, coup, nscale, outp, s == 7);
    }
}

// round 3
// speedup vs baseline: 1.1297x; 1.1297x over previous
#include <cuda_runtime.h>
#include <cuda_fp16.h>
#include <math.h>

#define LMAX      524288
#define NBS       512          // step grid
#define NTS       288          // step block (36*8 for epilogue reduce)
#define NB_PROJ   1184
#define NT_PROJ   256
#define RELMAX    64

// fp16 storage for projected K(+bias) and V: [L][32] halves, row-major.
__device__ __half g_kb[(size_t)LMAX * 32];
__device__ __half g_v [(size_t)LMAX * 32];
// per-block partials, transposed for coalesced epilogue reads: cell c (0..35), block b
__device__ float  g_part[36 * NBS];
__device__ float  g_z[32];
__device__ float  g_q[32];               // prescaled by 0.5 (= 1/sqrt(HEAD))
__device__ unsigned int g_cnt = 0;       // last-block detector (reset each step)

// -------------------- prologue: projections (half2 math) + init (block 0) ---
__global__ __launch_bounds__(NT_PROJ)
void k_project(const float* __restrict__ zp,
               const float* __restrict__ k_w, const float* __restrict__ k_b,
               const float* __restrict__ v_w, const float* __restrict__ v_b,
               const float* __restrict__ rel_bias,
               const int*   __restrict__ pos, int L,
               const float* __restrict__ cand,
               const float* __restrict__ q_w, const float* __restrict__ q_b)
{
    __shared__ __half2 swk2[512];
    __shared__ __half2 swv2[512];
    __shared__ float   sbk[32];
    __shared__ float   sbv[32];
    for (int t = threadIdx.x; t < 512; t += NT_PROJ) {
        swk2[t] = __floats2half2_rn(k_w[2*t], k_w[2*t+1]);
        swv2[t] = __floats2half2_rn(v_w[2*t], v_w[2*t+1]);
    }
    if (threadIdx.x < 32)      sbk[threadIdx.x]      = k_b[threadIdx.x];
    else if (threadIdx.x < 64) sbv[threadIdx.x - 32] = v_b[threadIdx.x - 32];

    // init z and q0 (exact fp32)
    if (blockIdx.x == 0 && threadIdx.x < 32) {
        int j = threadIdx.x;
        g_z[j] = cand[j];
        float acc = q_b[j];
#pragma unroll
        for (int i = 0; i < 32; i++) acc += cand[i] * q_w[j * 32 + i];
        g_q[j] = 0.5f * acc;
    }
    __syncthreads();

    const int off    = pos[0] - L + RELMAX;
    const int stride = gridDim.x * blockDim.x;

    for (int l = blockIdx.x * blockDim.x + threadIdx.x; l < L; l += stride) {
        // load row, convert to half2[16]
        __half2 xh[16];
        const float4* row = (const float4*)(zp + (size_t)l * 32);
#pragma unroll
        for (int c = 0; c < 8; c++) {
            float4 t = row[c];
            xh[2*c]   = __floats2half2_rn(t.x, t.y);
            xh[2*c+1] = __floats2half2_rn(t.z, t.w);
        }
        int idx = off + l;
        idx = idx < 0 ? 0 : (idx > 2 * RELMAX ? 2 * RELMAX : idx);
        const float* rb = rel_bias + idx * 32;

        __half2 outk[16], outv[16];
#pragma unroll
        for (int m = 0; m < 16; m++) {
            int j0 = 2 * m, j1 = 2 * m + 1;
            const __half2* wk0 = swk2 + j0 * 16;
            const __half2* wk1 = swk2 + j1 * 16;
            const __half2* wv0 = swv2 + j0 * 16;
            const __half2* wv1 = swv2 + j1 * 16;
            __half2 pk0 = __hmul2(xh[0], wk0[0]);
            __half2 pk1 = __hmul2(xh[0], wk1[0]);
            __half2 pv0 = __hmul2(xh[0], wv0[0]);
            __half2 pv1 = __hmul2(xh[0], wv1[0]);
#pragma unroll
            for (int i = 1; i < 16; i++) {
                pk0 = __hfma2(xh[i], wk0[i], pk0);
                pk1 = __hfma2(xh[i], wk1[i], pk1);
                pv0 = __hfma2(xh[i], wv0[i], pv0);
                pv1 = __hfma2(xh[i], wv1[i], pv1);
            }
            float2 fk0 = __half22float2(pk0);
            float2 fk1 = __half22float2(pk1);
            float2 fv0 = __half22float2(pv0);
            float2 fv1 = __half22float2(pv1);
            float2 rb2 = *(const float2*)(rb + j0);
            float k0 = fk0.x + fk0.y + sbk[j0] + rb2.x;
            float k1 = fk1.x + fk1.y + sbk[j1] + rb2.y;
            float v0 = fv0.x + fv0.y + sbv[j0];
            float v1 = fv1.x + fv1.y + sbv[j1];
            outk[m] = __floats2half2_rn(k0, k1);
            outv[m] = __floats2half2_rn(v0, v1);
        }
        int4* dk = (int4*)(g_kb + (size_t)l * 32);
        int4* dv = (int4*)(g_v  + (size_t)l * 32);
        const int4* sk = (const int4*)outk;
        const int4* sv = (const int4*)outv;
#pragma unroll
        for (int c = 0; c < 4; c++) { dk[c] = sk[c]; dv[c] = sv[c]; }
    }
}

// -------------------- fused step: streaming partials + last-block update ----
__global__ __launch_bounds__(NTS)
void k_step(int L,
            const float* __restrict__ o_w, const float* __restrict__ o_b,
            const float* __restrict__ q_w, const float* __restrict__ q_b,
            const float* __restrict__ coupling,
            const float* __restrict__ norm_scale,
            float* __restrict__ outp, int last)
{
    __half2 qh[16];
    {
        const float* q = g_q;
#pragma unroll
        for (int m = 0; m < 16; m++) qh[m] = __floats2half2_rn(q[2*m], q[2*m+1]);
    }

    float   s[4]   = {0.f, 0.f, 0.f, 0.f};
    __half2 acc[16];
#pragma unroll
    for (int m = 0; m < 16; m++) acc[m] = __floats2half2_rn(0.f, 0.f);

    const int stride = gridDim.x * blockDim.x;
    for (int l = blockIdx.x * blockDim.x + threadIdx.x; l < L; l += stride) {
        int4 kr[4], vr[4];
        const int4* kp = (const int4*)(g_kb + (size_t)l * 32);
        const int4* vp = (const int4*)(g_v  + (size_t)l * 32);
#pragma unroll
        for (int c = 0; c < 4; c++) { kr[c] = kp[c]; vr[c] = vp[c]; }
        const __half2* kh = (const __half2*)kr;
        const __half2* vh = (const __half2*)vr;
#pragma unroll
        for (int h = 0; h < 4; h++) {
            __half2 p = __hmul2(kh[4*h], qh[4*h]);
#pragma unroll
            for (int m = 1; m < 4; m++) p = __hfma2(kh[4*h+m], qh[4*h+m], p);
            float2 pf = __half22float2(p);
            float e = __expf(pf.x + pf.y);   // bounded scores, no max-sub
            s[h] += e;
            __half2 eh = __float2half2_rn(e);
#pragma unroll
            for (int m = 0; m < 4; m++)
                acc[4*h+m] = __hfma2(eh, vh[4*h+m], acc[4*h+m]);
        }
    }

    // pack 36 values (s + 32 acc) and tree-reduce within warp, then block
    float vals[36];
#pragma unroll
    for (int h = 0; h < 4; h++) {
        vals[h*9] = s[h];
#pragma unroll
        for (int m = 0; m < 4; m++) {
            float2 a = __half22float2(acc[4*h+m]);
            vals[h*9 + 1 + 2*m]     = a.x;
            vals[h*9 + 1 + 2*m + 1] = a.y;
        }
    }
#pragma unroll
    for (int t = 0; t < 36; t++) {
#pragma unroll
        for (int o = 16; o; o >>= 1)
            vals[t] += __shfl_down_sync(0xffffffffu, vals[t], o);
    }

    __shared__ float sred[NTS / 32][36];
    int wid = threadIdx.x >> 5;
    int lid = threadIdx.x & 31;
    if (lid == 0) {
#pragma unroll
        for (int t = 0; t < 36; t++) sred[wid][t] = vals[t];
    }
    __syncthreads();
    if (threadIdx.x < 36) {
        float r = 0.f;
#pragma unroll
        for (int w = 0; w < NTS / 32; w++) r += sred[w][threadIdx.x];
        g_part[threadIdx.x * NBS + blockIdx.x] = r;   // transposed layout
    }

    // ---- last-block epilogue: reduce partials + o-proj + mish + LN + next-q
    __shared__ bool amLast;
    __threadfence();
    if (threadIdx.x == 0) {
        unsigned int v = atomicAdd(&g_cnt, 1u);
        amLast = (v == (unsigned int)(gridDim.x - 1));
    }
    __syncthreads();
    if (!amLast) return;

    int c = threadIdx.x >> 3;      // 0..35
    int j = threadIdx.x & 7;       // 0..7
    float r = 0.f;
    const float* pp = g_part + c * NBS;
#pragma unroll 4
    for (int b = j; b < NBS; b += 8) r += pp[b];
#pragma unroll
    for (int o = 4; o; o >>= 1) r += __shfl_down_sync(0xffffffffu, r, o, 8);

    __shared__ float red[36];
    __shared__ float sout[32];
    __shared__ float sz[32];
    if (j == 0) red[c] = r;
    __syncthreads();

    int tid = threadIdx.x;
    if (tid < 32) {
        int h = tid >> 3;
        sout[tid] = red[h * 9 + 1 + (tid & 7)] / red[h * 9];
    }
    __syncthreads();
    if (tid < 32) {
        float m = o_b[tid];
#pragma unroll
        for (int i = 0; i < 32; i++) m += sout[i] * o_w[tid * 32 + i];
        float zz = g_z[tid] + coupling[0] * m;
        float sp = (zz > 15.f) ? zz : log1pf(__expf(zz));
        sz[tid] = zz * tanhf(sp);
    }
    __syncthreads();
    if (tid < 32) {
        int par = tid & 1;
        float mn = 0.f;
#pragma unroll
        for (int d = 0; d < 16; d++) mn += sz[2 * d + par];
        mn *= (1.f / 16.f);
        float var = 0.f;
#pragma unroll
        for (int d = 0; d < 16; d++) { float dd = sz[2 * d + par] - mn; var += dd * dd; }
        var *= (1.f / 16.f);
        float zn = (sz[tid] - mn) * rsqrtf(var + 1e-5f) * norm_scale[0];
        g_z[tid] = zn;
        sout[tid] = zn;
        if (last) outp[tid] = zn;
    }
    __syncthreads();
    if (tid < 32) {
        float qq = q_b[tid];
#pragma unroll
        for (int i = 0; i < 32; i++) qq += sout[i] * q_w[tid * 32 + i];
        g_q[tid] = 0.5f * qq;
    }
    if (tid == 0) g_cnt = 0;   // reset for next step / next replay
}

extern "C" void kernel_launch(void* const* d_in, const int* in_sizes, int n_in,
                              void* d_out, int out_size)
{
    const float* cand   = (const float*)d_in[0];
    const float* zp     = (const float*)d_in[1];
    const float* q_w    = (const float*)d_in[2];
    const float* q_b    = (const float*)d_in[3];
    const float* k_w    = (const float*)d_in[4];
    const float* k_b    = (const float*)d_in[5];
    const float* v_w    = (const float*)d_in[6];
    const float* v_b    = (const float*)d_in[7];
    const float* o_w    = (const float*)d_in[8];
    const float* o_b    = (const float*)d_in[9];
    const float* rbias  = (const float*)d_in[10];
    const float* coup   = (const float*)d_in[11];
    const float* nscale = (const float*)d_in[12];
    const int*   pos    = (const int*)  d_in[13];

    int L = in_sizes[1] / 32;
    float* outp = (float*)d_out;

    k_project<<<NB_PROJ, NT_PROJ>>>(zp, k_w, k_b, v_w, v_b, rbias, pos, L,
                                    cand, q_w, q_b);
    for (int s = 0; s < 8; s++)
        k_step<<<NBS, NTS>>>(L, o_w, o_b, q_w, q_b, coup, nscale, outp, s == 7);
}

// round 6
// speedup vs baseline: 1.7097x; 1.5133x over previous
#include <cuda_runtime.h>
#include <cuda_fp16.h>
#include <math.h>

#define LMAX 524288
#define NBS  432          // step grid
#define NTB  128          // step block
#define NBC  592          // convert grid
#define NTC  256          // convert block
typedef unsigned long long ull;

// fp16 copy of z_past: [L][32] halves (16B-aligned for int4 access)
__device__ __align__(16) __half g_zh[(size_t)LMAX * 32];
// per-block partials: [block][132]  (c<4: s_h, c=4+h*32+i: S_h[i])
__device__ float  g_part[NBS * 132];
__device__ float  g_z[32];
__device__ float  g_uf[4][32];     // fp32 u (for epilogue correction)
__device__ __half2 g_uh[4][16];    // half2 u (for mainloop scores)
__device__ float  g_f[4][64];      // correction factors for rows l<64
__device__ unsigned int g_cnt = 0;

// ---------------- f32x2 helpers ----------------
__device__ __forceinline__ ull f2pack(float lo, float hi) {
    ull r; asm("mov.b64 %0,{%1,%2};" : "=l"(r) : "f"(lo), "f"(hi)); return r;
}
__device__ __forceinline__ void f2unpack(ull v, float& lo, float& hi) {
    asm("mov.b64 {%0,%1},%2;" : "=f"(lo), "=f"(hi) : "l"(v));
}
__device__ __forceinline__ void ffma2(ull& d, ull a, ull b) {
    asm("fma.rn.f32x2 %0,%1,%2,%0;" : "+l"(d) : "l"(a), "l"(b));
}
__device__ __forceinline__ ull fadd2(ull a, ull b) {
    ull r; asm("add.rn.f32x2 %0,%1,%2;" : "=l"(r) : "l"(a), "l"(b)); return r;
}

// ---- shared epilogue math: from smem sq (=0.5*q) compute u (g_uf/g_uh) and f (g_f)
__device__ __forceinline__ void compute_u_f(const float* sq, float (*su)[32],
                                            const float* k_w, const float* rbias,
                                            int off, int tid, int nthreads)
{
    if (tid < 128) {
        int h = tid >> 5, i = tid & 31;
        float u = 0.f;
#pragma unroll
        for (int j = 0; j < 8; j++) u += sq[8*h + j] * k_w[(8*h + j) * 32 + i];
        g_uf[h][i] = u;
        su[h][i] = u;
    }
    __syncthreads();
    if (tid < 64) {
        int h = tid >> 4, m = tid & 15;
        g_uh[h][m] = __floats2half2_rn(su[h][2*m], su[h][2*m+1]);
    }
    for (int task = tid; task < 256; task += nthreads) {
        int h = task >> 6, l = task & 63;
        int idx = off + l;
        idx = idx < 0 ? 0 : (idx > 128 ? 128 : idx);
        float d = 0.f;
#pragma unroll
        for (int j = 0; j < 8; j++)
            d += sq[8*h + j] * (rbias[idx * 32 + 8*h + j] - rbias[128 * 32 + 8*h + j]);
        g_f[h][l] = __expf(d);
    }
}

// ---------------- convert: z_past -> fp16, plus step-0 init (block 0) -------
__global__ __launch_bounds__(NTC)
void k_convert(const float* __restrict__ zp, int L,
               const float* __restrict__ cand,
               const float* __restrict__ q_w, const float* __restrict__ q_b,
               const float* __restrict__ k_w, const float* __restrict__ rbias,
               const int* __restrict__ pos)
{
    if (blockIdx.x == 0) {
        __shared__ float scand[32], sq[32], su[4][32];
        int tid = threadIdx.x;
        if (tid < 32) { scand[tid] = cand[tid]; g_z[tid] = cand[tid]; }
        __syncthreads();
        if (tid < 32) {
            float qq = q_b[tid];
#pragma unroll
            for (int i = 0; i < 32; i++) qq += scand[i] * q_w[tid * 32 + i];
            sq[tid] = 0.5f * qq;
        }
        __syncthreads();
        compute_u_f(sq, su, k_w, rbias, pos[0] - L + 64, tid, NTC);
        __syncthreads();
    }
    const int stride = gridDim.x * blockDim.x;
    for (int l = blockIdx.x * blockDim.x + threadIdx.x; l < L; l += stride) {
        const float4* row = (const float4*)(zp + (size_t)l * 32);
        __half2 h[16];
#pragma unroll
        for (int c = 0; c < 8; c++) {
            float4 t = row[c];
            h[2*c]   = __floats2half2_rn(t.x, t.y);
            h[2*c+1] = __floats2half2_rn(t.z, t.w);
        }
        int4* dst = (int4*)(g_zh + (size_t)l * 32);
        const int4* src = (const int4*)h;
#pragma unroll
        for (int c = 0; c < 4; c++) dst[c] = src[c];
    }
}

// ---------------- fused step: streaming + last-block epilogue ---------------
__global__ __launch_bounds__(NTB, 3)
void k_step(int L,
            const float* __restrict__ k_w,
            const float* __restrict__ v_w, const float* __restrict__ v_b,
            const float* __restrict__ o_w, const float* __restrict__ o_b,
            const float* __restrict__ q_w, const float* __restrict__ q_b,
            const float* __restrict__ rbias,
            const float* __restrict__ coupling,
            const float* __restrict__ norm_scale,
            const int* __restrict__ pos,
            float* __restrict__ outp, int last)
{
    const int tid  = threadIdx.x;
    const int gtid = blockIdx.x * NTB + tid;
    const int par  = gtid & 1;          // lane parity: which 16 components
    const int lane = tid & 31;

    __half2 uh[4][8];
#pragma unroll
    for (int h = 0; h < 4; h++)
#pragma unroll
        for (int m = 0; m < 8; m++) uh[h][m] = g_uh[h][par * 8 + m];

    float s[4] = {0.f, 0.f, 0.f, 0.f};
    ull acc[4][8];
#pragma unroll
    for (int h = 0; h < 4; h++)
#pragma unroll
        for (int m = 0; m < 8; m++) acc[h][m] = 0ull;

    const int rstride = (NBS * NTB) >> 1;
    for (int r = gtid >> 1; r < L; r += rstride) {
        int4 a[2];
        const int4* zp = (const int4*)(g_zh + (size_t)r * 32 + par * 16);
        a[0] = zp[0]; a[1] = zp[1];
        const __half2* zh = (const __half2*)a;

        float e[4];
#pragma unroll
        for (int h = 0; h < 4; h++) {
            __half2 p = __hmul2(zh[0], uh[h][0]);
#pragma unroll
            for (int m = 1; m < 8; m++) p = __hfma2(zh[m], uh[h][m], p);
            float2 pf = __half22float2(p);
            float sc = pf.x + pf.y;
            sc += __shfl_xor_sync(0xffffffffu, sc, 1);
            e[h] = __expf(sc);             // bounded scores; constants cancel
            s[h] += e[h];
        }
        ull zf[8];
#pragma unroll
        for (int m = 0; m < 8; m++) {
            float2 zz = __half22float2(zh[m]);
            zf[m] = f2pack(zz.x, zz.y);
        }
#pragma unroll
        for (int h = 0; h < 4; h++) {
            ull ep = f2pack(e[h], e[h]);
#pragma unroll
            for (int m = 0; m < 8; m++) ffma2(acc[h][m], ep, zf[m]);
        }
    }

    // warp reduction among same-parity lanes (offsets 2,4,8,16)
#pragma unroll
    for (int o = 2; o <= 16; o <<= 1) {
#pragma unroll
        for (int h = 0; h < 4; h++) {
            s[h] += __shfl_xor_sync(0xffffffffu, s[h], o);
#pragma unroll
            for (int m = 0; m < 8; m++)
                acc[h][m] = fadd2(acc[h][m], __shfl_xor_sync(0xffffffffu, acc[h][m], o));
        }
    }

    __shared__ float sm_s[4][4];        // parity-0 only (parities are equal)
    __shared__ float sm_S[4][4][32];
    int w = tid >> 5;
    if (lane < 2) {
#pragma unroll
        for (int h = 0; h < 4; h++) {
            if (par == 0) sm_s[w][h] = s[h];
#pragma unroll
            for (int m = 0; m < 8; m++) {
                float lo, hi;
                f2unpack(acc[h][m], lo, hi);
                sm_S[w][h][par * 16 + 2*m]     = lo;
                sm_S[w][h][par * 16 + 2*m + 1] = hi;
            }
        }
    }
    __syncthreads();
    for (int c = tid; c < 132; c += NTB) {          // all 132 cells covered
        float r;
        if (c < 4) {
            r = sm_s[0][c] + sm_s[1][c] + sm_s[2][c] + sm_s[3][c];
        } else {
            int h = (c - 4) >> 5, i = (c - 4) & 31;
            r = sm_S[0][h][i] + sm_S[1][h][i] + sm_S[2][h][i] + sm_S[3][h][i];
        }
        g_part[blockIdx.x * 132 + c] = r;
    }

    // ---- last-block epilogue ----
    __shared__ bool amLast;
    __threadfence();
    if (tid == 0) {
        unsigned int v = atomicAdd(&g_cnt, 1u);
        amLast = (v == (unsigned int)(gridDim.x - 1));
    }
    __syncthreads();
    if (!amLast) return;

    __shared__ float red[132];
    for (int c = tid; c < 132; c += NTB) {
        float r = 0.f;
        const float* pp = g_part + c;
#pragma unroll 4
        for (int b = 0; b < NBS; b++) r += pp[b * 132];
        red[c] = r;
    }
    // load first 64 rows of z (for the rel-bias correction region)
    __shared__ __align__(16) __half szh[64 * 32];
    for (int t = tid; t < 256; t += NTB)
        ((int4*)szh)[t] = ((const int4*)g_zh)[t];
    __shared__ float sw[4][64];
    __syncthreads();

    for (int task = tid; task < 256; task += NTB) {
        int h = task >> 6, l = task & 63;
        float sc = 0.f;
#pragma unroll
        for (int i = 0; i < 32; i++) sc += g_uf[h][i] * __half2float(szh[l * 32 + i]);
        sw[h][l] = (g_f[h][l] - 1.f) * __expf(sc);
    }
    __syncthreads();
    {
        int h = tid >> 5, i = tid & 31;
        float d = 0.f;
#pragma unroll
        for (int l = 0; l < 64; l++) d += sw[h][l] * __half2float(szh[l * 32 + i]);
        red[4 + h * 32 + i] += d;
        if (tid < 4) {
            float ds = 0.f;
#pragma unroll
            for (int l = 0; l < 64; l++) ds += sw[tid][l];
            red[tid] += ds;
        }
    }
    __syncthreads();

    __shared__ float sout[32], szl[32], sq[32], su[4][32];
    if (tid < 32) {
        int h = tid >> 3;
        float inv = 1.f / red[h];
        float o = v_b[tid];
#pragma unroll
        for (int i = 0; i < 32; i++) o += v_w[tid * 32 + i] * (red[4 + h * 32 + i] * inv);
        sout[tid] = o;
    }
    __syncthreads();
    if (tid < 32) {
        float m = o_b[tid];
#pragma unroll
        for (int i = 0; i < 32; i++) m += sout[i] * o_w[tid * 32 + i];
        float zz = g_z[tid] + coupling[0] * m;
        float sp = (zz > 15.f) ? zz : log1pf(__expf(zz));
        szl[tid] = zz * tanhf(sp);
    }
    __syncthreads();
    if (tid < 32) {
        int p = tid & 1;
        float mn = 0.f;
#pragma unroll
        for (int d = 0; d < 16; d++) mn += szl[2 * d + p];
        mn *= (1.f / 16.f);
        float var = 0.f;
#pragma unroll
        for (int d = 0; d < 16; d++) { float dd = szl[2 * d + p] - mn; var += dd * dd; }
        var *= (1.f / 16.f);
        float zn = (szl[tid] - mn) * rsqrtf(var + 1e-5f) * norm_scale[0];
        g_z[tid] = zn;
        sout[tid] = zn;
        if (last) outp[tid] = zn;
    }
    __syncthreads();
    if (tid < 32) {
        float qq = q_b[tid];
#pragma unroll
        for (int i = 0; i < 32; i++) qq += sout[i] * q_w[tid * 32 + i];
        sq[tid] = 0.5f * qq;
    }
    __syncthreads();
    compute_u_f(sq, su, k_w, rbias, pos[0] - L + 64, tid, NTB);
    if (tid == 0) g_cnt = 0;
}

extern "C" void kernel_launch(void* const* d_in, const int* in_sizes, int n_in,
                              void* d_out, int out_size)
{
    const float* cand   = (const float*)d_in[0];
    const float* zp     = (const float*)d_in[1];
    const float* q_w    = (const float*)d_in[2];
    const float* q_b    = (const float*)d_in[3];
    const float* k_w    = (const float*)d_in[4];
    const float* v_w    = (const float*)d_in[6];
    const float* v_b    = (const float*)d_in[7];
    const float* o_w    = (const float*)d_in[8];
    const float* o_b    = (const float*)d_in[9];
    const float* rbias  = (const float*)d_in[10];
    const float* coup   = (const float*)d_in[11];
    const float* nscale = (const float*)d_in[12];
    const int*   pos    = (const int*)  d_in[13];

    int L = in_sizes[1] / 32;
    float* outp = (float*)d_out;

    k_convert<<<NBC, NTC>>>(zp, L, cand, q_w, q_b, k_w, rbias, pos);
    for (int s = 0; s < 8; s++)
        k_step<<<NBS, NTB>>>(L, k_w, v_w, v_b, o_w, o_b, q_w, q_b,
                             rbias, coup, nscale, pos, outp, s == 7);
}